// round 13
// baseline (speedup 1.0000x reference)
#include <cuda_runtime.h>
#include <cuda_bf16.h>
#include <cstdint>

#define FULL_MASK 0xFFFFFFFFu

constexpr int E_EDGES = 65536;
constexpr int F_DIM   = 128;
constexpr int D_DEG   = 32;
constexpr int THREADS = 256;
constexpr int BLOCKS  = 888;                      // 148 SMs x 6 resident blocks
constexpr int N_WARPS = BLOCKS * (THREADS / 32);  // 7104 warps, ~9 edges each
constexpr int WPB     = THREADS / 32;             // warps per block

__device__ __forceinline__ void cpa16(uint32_t smem_dst, const void* gsrc) {
    asm volatile("cp.async.cg.shared.global [%0], [%1], 16;" :: "r"(smem_dst), "l"(gsrc));
}
#define CP_COMMIT()   asm volatile("cp.async.commit_group;" ::: "memory")
#define CP_WAIT1()    asm volatile("cp.async.wait_group 1;" ::: "memory")
#define CP_WAIT_ALL() asm volatile("cp.async.wait_group 0;" ::: "memory")

// One warp per edge, grid-stride, double-buffered PER-WARP cp.async staging:
// next edge's 2 x-rows + 2 nbr-rows are copied into this warp's smem slot with
// zero register cost while the current edge computes. Warp-scoped waits only —
// no block barriers (R6's mistake), no register-held rows (R9/R10's mistake).
__global__ void __launch_bounds__(THREADS, 6)
ncn_kernel(const float* __restrict__ x,
           const int*   __restrict__ nbr,
           const int*   __restrict__ tar_ei,
           const float* __restrict__ W,
           const float* __restrict__ b,
           float*       __restrict__ out)
{
    // [warp][stage][row(i,j)] : x rows 512B each, nbr rows 128B each
    __shared__ __align__(16) float xbuf[WPB][2][2][F_DIM];
    __shared__ __align__(16) int   nbuf[WPB][2][2][D_DEG];

    const int lane  = threadIdx.x & 31;
    const int wloc  = threadIdx.x >> 5;
    const int w     = (blockIdx.x * blockDim.x + threadIdx.x) >> 5;

    const uint32_t xb = (uint32_t)__cvta_generic_to_shared(&xbuf[wloc][0][0][0]);
    const uint32_t nb = (uint32_t)__cvta_generic_to_shared(&nbuf[wloc][0][0][0]);

    // Per-lane weight slices (reused every iter -> keep L1 path)
    const float4 w0 = __ldg(&reinterpret_cast<const float4*>(W)[lane]);
    const float4 w1 = __ldg(&reinterpret_cast<const float4*>(W + F_DIM)[lane]);
    const float  bv = __ldg(b);

    const float4* xv = reinterpret_cast<const float4*>(x);

    // ---- prologue: stage edge e into buffer 0; prefetch idx for e+stride ----
    int e  = w;                               // N_WARPS < E, every warp has work
    {
        const int i0 = __ldg(tar_ei + e);
        const int j0 = __ldg(tar_ei + E_EDGES + e);
        cpa16(xb + lane * 16,        x + (size_t)i0 * F_DIM + lane * 4);
        cpa16(xb + 512 + lane * 16,  x + (size_t)j0 * F_DIM + lane * 4);
        if (lane < 16) {
            const int r = (lane < 8) ? i0 : j0;          // lanes 0-7: ni, 8-15: nj
            cpa16(nb + (lane >> 3) * 128 + (lane & 7) * 16,
                  nbr + (size_t)r * D_DEG + (lane & 7) * 4);
        }
        CP_COMMIT();
    }
    int e1  = e + N_WARPS;
    int ec1 = min(e1, E_EDGES - 1);
    int i1  = __ldg(tar_ei + ec1);
    int j1  = __ldg(tar_ei + E_EDGES + ec1);

    int s = 0;
    while (true) {
        // ---- issue next edge's staging into stage s^1 (idx already in regs) ----
        {
            const int t = s ^ 1;
            cpa16(xb + t * 1024 + lane * 16,       x + (size_t)i1 * F_DIM + lane * 4);
            cpa16(xb + t * 1024 + 512 + lane * 16, x + (size_t)j1 * F_DIM + lane * 4);
            if (lane < 16) {
                const int r = (lane < 8) ? i1 : j1;
                cpa16(nb + t * 256 + (lane >> 3) * 128 + (lane & 7) * 16,
                      nbr + (size_t)r * D_DEG + (lane & 7) * 4);
            }
            CP_COMMIT();
        }
        // idx for edge after next (distance-2 prefetch)
        const int e2  = e1 + N_WARPS;
        const int ec2 = min(e2, E_EDGES - 1);
        const int i2  = __ldg(tar_ei + ec2);
        const int j2  = __ldg(tar_ei + E_EDGES + ec2);

        // ---- current stage ready (all groups except the just-issued one) ----
        CP_WAIT1();
        __syncwarp();

        const float4 a = reinterpret_cast<const float4*>(xbuf[wloc][s][0])[lane];
        const float4 c = reinterpret_cast<const float4*>(xbuf[wloc][s][1])[lane];
        const int ni_l = nbuf[wloc][s][0][lane];
        const int nj_l = nbuf[wloc][s][1][lane];

        float acc = a.x*c.x*w0.x + a.y*c.y*w0.y + a.z*c.z*w0.z + a.w*c.w*w0.w;

        // lower_bound of ni_l in sorted distributed nj (clip + equality,
        // matching jnp.searchsorted semantics in the reference).
        int lo = 0, hi = D_DEG - 1;
        #pragma unroll
        for (int st = 0; st < 5; ++st) {
            const int mid = (lo + hi) >> 1;
            const int v   = __shfl_sync(FULL_MASK, nj_l, mid);
            if (v < ni_l) lo = mid + 1; else hi = mid;
        }
        const bool hit = (__shfl_sync(FULL_MASK, nj_l, lo) == ni_l);

        // Rare common-neighbor contributions (warp-uniform mask).
        unsigned hm = __ballot_sync(FULL_MASK, hit);
        while (hm) {
            const int h = __ffs(hm) - 1; hm &= hm - 1u;
            const int cn = __shfl_sync(FULL_MASK, ni_l, h);
            const float4 xc = __ldg(&xv[(size_t)cn * (F_DIM/4) + lane]);
            acc += xc.x*w1.x + xc.y*w1.y + xc.z*w1.z + xc.w*w1.w;
        }

        // Warp reduction (butterfly).
        #pragma unroll
        for (int off = 16; off >= 1; off >>= 1)
            acc += __shfl_down_sync(FULL_MASK, acc, off);

        if (lane == 0) out[e] = acc + bv;

        __syncwarp();   // all lanes done reading stage s before it is refilled

        if (e1 >= E_EDGES) break;
        e = e1; e1 = e2;
        i1 = i2; j1 = j2;
        s ^= 1;
    }

    CP_WAIT_ALL();      // drain outstanding async copies before exit
}

extern "C" void kernel_launch(void* const* d_in, const int* in_sizes, int n_in,
                              void* d_out, int out_size)
{
    const float* x      = (const float*)d_in[0];
    const int*   nbr    = (const int*)  d_in[1];
    const int*   tar_ei = (const int*)  d_in[2];
    const float* W      = (const float*)d_in[3];
    const float* b      = (const float*)d_in[4];
    float*       out    = (float*)d_out;

    ncn_kernel<<<BLOCKS, THREADS>>>(x, nbr, tar_ei, W, b, out);
}